// round 1
// baseline (speedup 1.0000x reference)
#include <cuda_runtime.h>
#include <cuda_bf16.h>
#include <cstdint>

// Problem dims
#define T_STEPS 2048
#define B_SZ    32
#define D_SZ    512
#define H_SZ    512
#define G_SZ    2048   // 4*H
#define NBLK    128    // persistent blocks (<=148 SMs -> co-resident)

// ---------------- device scratch (static, no runtime alloc) ----------------
// x_proj stored TRANSPOSED: [T][4H][B]  (so recurrent reads are coalesced & partitioned)
__device__ float g_xproj[(size_t)T_STEPS * G_SZ * B_SZ];   // 512 MB
__device__ float g_m[2][H_SZ * B_SZ];                      // m double buffer, [h][b]
__device__ int   g_bar;

// ---------------- reset kernel (runs every launch; no static guards) -------
__global__ void reset_kernel() {
    int tid = blockIdx.x * blockDim.x + threadIdx.x;
    if (tid == 0) g_bar = 0;
    for (int i = tid; i < H_SZ * B_SZ; i += blockDim.x * gridDim.x)
        g_m[0][i] = 0.0f;
}

// ---------------- phase 1: x_proj GEMM (SIMT fp32, 128x128x16 tile) --------
// A = input [M=T*B][K=512] row-major, B = W_x [512][2048] row-major.
// C written transposed as [t][n][b].
__global__ __launch_bounds__(256) void xproj_gemm(
    const float* __restrict__ A, const float* __restrict__ Bm,
    const float* __restrict__ bias)
{
    __shared__ float As[16][132];   // [k][m], padded
    __shared__ float Bs[16][128];   // [k][n]

    int tid = threadIdx.x;
    int n0 = blockIdx.x * 128;
    int m0 = blockIdx.y * 128;
    int tx = tid & 15;      // n-tile
    int ty = tid >> 4;      // m-tile

    float acc[8][8];
#pragma unroll
    for (int i = 0; i < 8; i++)
#pragma unroll
        for (int j = 0; j < 8; j++) acc[i][j] = 0.0f;

    for (int k0 = 0; k0 < D_SZ; k0 += 16) {
        // A tile: 128 m x 16 k  (transpose into As)
#pragma unroll
        for (int li = 0; li < 2; li++) {
            int idx = tid + li * 256;           // 0..511
            int row = idx >> 2;                 // 0..127
            int kq  = (idx & 3) << 2;           // 0,4,8,12
            float4 v = *(const float4*)(A + (size_t)(m0 + row) * D_SZ + k0 + kq);
            As[kq + 0][row] = v.x;
            As[kq + 1][row] = v.y;
            As[kq + 2][row] = v.z;
            As[kq + 3][row] = v.w;
        }
        // B tile: 16 k x 128 n
#pragma unroll
        for (int li = 0; li < 2; li++) {
            int idx = tid + li * 256;
            int kr  = idx >> 5;                 // 0..15
            int nq  = (idx & 31) << 2;          // 0..124
            *(float4*)&Bs[kr][nq] = *(const float4*)(Bm + (size_t)(k0 + kr) * G_SZ + n0 + nq);
        }
        __syncthreads();
#pragma unroll
        for (int k = 0; k < 16; k++) {
            float av[8], bv[8];
            *(float4*)&av[0] = *(float4*)&As[k][ty * 8];
            *(float4*)&av[4] = *(float4*)&As[k][ty * 8 + 4];
            *(float4*)&bv[0] = *(float4*)&Bs[k][tx * 8];
            *(float4*)&bv[4] = *(float4*)&Bs[k][tx * 8 + 4];
#pragma unroll
            for (int i = 0; i < 8; i++)
#pragma unroll
                for (int j = 0; j < 8; j++) acc[i][j] += av[i] * bv[j];
        }
        __syncthreads();
    }

    // epilogue: write [t][n][b]; thread's 8 m-rows are 8 consecutive b of one t
    int mrow = m0 + ty * 8;
    int t  = mrow >> 5;
    int b0 = mrow & 31;
#pragma unroll
    for (int j = 0; j < 8; j++) {
        int n = n0 + tx * 8 + j;
        float bb = bias[n];
        float4 v0 = make_float4(acc[0][j] + bb, acc[1][j] + bb, acc[2][j] + bb, acc[3][j] + bb);
        float4 v1 = make_float4(acc[4][j] + bb, acc[5][j] + bb, acc[6][j] + bb, acc[7][j] + bb);
        float* dst = g_xproj + ((size_t)t * G_SZ + n) * B_SZ + b0;
        *(float4*)dst       = v0;
        *(float4*)(dst + 4) = v1;
    }
}

// ---------------- phase 2: persistent recurrent kernel ---------------------
// 128 blocks x 256 threads. Block owns 4 h-columns (16 gate columns).
// SMEM: m_s [512][36] (padded), w_s [512][20], xp_s [16][32], pad_s [32].
#define MS_STRIDE 36
#define WS_STRIDE 20
#define SMEM_FLOATS (H_SZ * MS_STRIDE + H_SZ * WS_STRIDE + 16 * B_SZ + 32)

__device__ __forceinline__ float fsig(float x)  { return 1.0f / (1.0f + __expf(-x)); }
__device__ __forceinline__ float ftanh(float x) { return 1.0f - 2.0f / (__expf(2.0f * x) + 1.0f); }

__global__ __launch_bounds__(256, 1) void lstm_kernel(
    const float* __restrict__ paddings,
    const float* __restrict__ W_h,
    float* __restrict__ out,
    int write_final)
{
    extern __shared__ float smem[];
    float* m_s   = smem;                              // [512][36]
    float* w_s   = m_s + H_SZ * MS_STRIDE;            // [512][20] (16 used)
    float* xp_s  = w_s + H_SZ * WS_STRIDE;            // [16 cc][32 b]
    float* pad_s = xp_s + 16 * B_SZ;                  // [32]

    const int tid = threadIdx.x;
    const int bid = blockIdx.x;
    const int h_base = bid * 4;

    // Load W_h slice: column cc = j*4 + g  ->  global col g*512 + h_base + j
    for (int idx = tid; idx < H_SZ * 16; idx += 256) {
        int k  = idx >> 4;
        int cc = idx & 15;
        int g  = cc & 3;
        int j  = cc >> 2;
        w_s[k * WS_STRIDE + cc] = W_h[(size_t)k * G_SZ + g * H_SZ + h_base + j];
    }

    const int l  = tid & 31;          // lane = K-split index
    const int w  = tid >> 5;          // warp = (b-tile, c-tile)
    const int bt = w & 3;
    const int ct = w >> 2;
    const int b0  = bt * 8;
    const int cc0 = ct * 8;

    // per-lane elementwise cell (lanes < 16): (b_c, j_c)
    const int bb_c = l & 7;
    const int jj_c = l >> 3;
    const int b_c  = b0 + bb_c;
    const int j_c  = ct * 2 + jj_c;       // block-local j 0..3
    const int h_c  = h_base + j_c;

    float c_reg = 0.0f;

#pragma unroll 1
    for (int s = 0; s < T_STEPS; s++) {
        const float* msrc = g_m[s & 1];
        // load m (64KB): 512 rows x 8 quads
#pragma unroll
        for (int li = 0; li < 16; li++) {
            int idx = tid + li * 256;
            int k = idx >> 3;
            int q = (idx & 7) << 2;
            *(float4*)&m_s[k * MS_STRIDE + q] = *(const float4*)(msrc + k * B_SZ + q);
        }
        // load xp slice: 16 cc x 32 b = 128 float4
        if (tid < 128) {
            int cc = tid >> 3;
            int q  = (tid & 7) << 2;
            int g  = cc & 3;
            int j  = cc >> 2;
            int col = g * H_SZ + h_base + j;
            *(float4*)&xp_s[cc * B_SZ + q] =
                *(const float4*)(g_xproj + ((size_t)s * G_SZ + col) * B_SZ + q);
        }
        if (tid >= 224) pad_s[tid - 224] = paddings[s * B_SZ + (tid - 224)];
        __syncthreads();

        // m @ W_h slice: warp tile 8b x 8cc, lane K-split 32
        float acc[8][8];
#pragma unroll
        for (int x = 0; x < 8; x++)
#pragma unroll
            for (int y = 0; y < 8; y++) acc[x][y] = 0.0f;

#pragma unroll
        for (int i = 0; i < 16; i++) {
            int k = (i << 5) + l;
            float mv[8], wv[8];
            *(float4*)&mv[0] = *(float4*)&m_s[k * MS_STRIDE + b0];
            *(float4*)&mv[4] = *(float4*)&m_s[k * MS_STRIDE + b0 + 4];
            *(float4*)&wv[0] = *(float4*)&w_s[k * WS_STRIDE + cc0];
            *(float4*)&wv[4] = *(float4*)&w_s[k * WS_STRIDE + cc0 + 4];
#pragma unroll
            for (int x = 0; x < 8; x++)
#pragma unroll
                for (int y = 0; y < 8; y++) acc[x][y] += mv[x] * wv[y];
        }

        // butterfly reduce over 32-way K-split
#pragma unroll
        for (int off = 16; off > 0; off >>= 1)
#pragma unroll
            for (int x = 0; x < 8; x++)
#pragma unroll
                for (int y = 0; y < 8; y++)
                    acc[x][y] += __shfl_xor_sync(0xffffffffu, acc[x][y], off);

        if (l < 16) {
            int ccb = jj_c * 4;
            float xi = acc[bb_c][ccb + 0] + xp_s[(j_c * 4 + 0) * B_SZ + b_c];
            float xf = acc[bb_c][ccb + 1] + xp_s[(j_c * 4 + 1) * B_SZ + b_c];
            float xg = acc[bb_c][ccb + 2] + xp_s[(j_c * 4 + 2) * B_SZ + b_c];
            float xo = acc[bb_c][ccb + 3] + xp_s[(j_c * 4 + 3) * B_SZ + b_c];
            float p     = pad_s[b_c];
            float mprev = m_s[h_c * MS_STRIDE + b_c];

            float ii = fsig(xi), ff = fsig(xf), gg = ftanh(xg), oo = fsig(xo);
            float cn = ff * c_reg + ii * gg;
            float mn = oo * ftanh(cn);
            float m2 = mn + (mprev - mn) * p;
            float c2 = cn + (c_reg - cn) * p;
            c_reg = c2;

            g_m[(s + 1) & 1][h_c * B_SZ + b_c] = m2;
            out[((size_t)s * B_SZ + b_c) * H_SZ + h_c] = m2;
            if (write_final && s == T_STEPS - 1) {
                size_t base = (size_t)T_STEPS * B_SZ * H_SZ;
                out[base + (size_t)b_c * H_SZ + h_c] = m2;
                out[base + (size_t)B_SZ * H_SZ + (size_t)b_c * H_SZ + h_c] = c2;
            }
        }

        // ---- grid barrier (monotonic count; reset kernel zeroes g_bar) ----
        __syncthreads();                         // all block writes program-ordered
        if (tid == 0) {
            __threadfence();                     // release (cumulative w/ bar.sync)
            atomicAdd(&g_bar, 1);
            int target = NBLK * (s + 1);
            while (*(volatile int*)&g_bar < target) { }
            __threadfence();                     // acquire
        }
        __syncthreads();
    }
}

// ---------------- launch ----------------------------------------------------
extern "C" void kernel_launch(void* const* d_in, const int* in_sizes, int n_in,
                              void* d_out, int out_size)
{
    const float* input = (const float*)d_in[0];   // [T,B,D]
    const float* padd  = (const float*)d_in[1];   // [T,B,1]
    const float* W_x   = (const float*)d_in[2];   // [D,4H]
    const float* W_h   = (const float*)d_in[3];   // [H,4H]
    const float* bias  = (const float*)d_in[4];   // [4H]
    float* out = (float*)d_out;

    const size_t smem_bytes = (size_t)SMEM_FLOATS * sizeof(float);
    cudaFuncSetAttribute(lstm_kernel, cudaFuncAttributeMaxDynamicSharedMemorySize,
                         (int)smem_bytes);

    int write_final =
        ((size_t)out_size >= (size_t)T_STEPS * B_SZ * H_SZ + 2u * B_SZ * H_SZ) ? 1 : 0;

    reset_kernel<<<1, 256>>>();
    xproj_gemm<<<dim3(G_SZ / 128, (T_STEPS * B_SZ) / 128), 256>>>(input, W_x, bias);
    lstm_kernel<<<NBLK, 256, smem_bytes>>>(padd, W_h, out, write_final);
}

// round 2
// speedup vs baseline: 1.0349x; 1.0349x over previous
#include <cuda_runtime.h>
#include <cuda_bf16.h>
#include <cstdint>

#define T_STEPS 2048
#define B_SZ    32
#define D_SZ    512
#define H_SZ    512
#define G_SZ    2048
#define NBLK    128

// ---------------- device scratch ----------------
__device__ float g_xproj[(size_t)T_STEPS * G_SZ * B_SZ];   // [T][4H][B]
__device__ float g_m[2][H_SZ * B_SZ];                      // [h][b]
__device__ int   g_bar;

// ---------------- cp.async helpers ----------------
#define CP_ASYNC16(dst_u32, src_ptr) \
    asm volatile("cp.async.cg.shared.global [%0], [%1], 16;\n" :: "r"(dst_u32), "l"(src_ptr))
#define CP_COMMIT() asm volatile("cp.async.commit_group;\n")
#define CP_WAIT(N)  asm volatile("cp.async.wait_group %0;\n" :: "n"(N))

// ---------------- phase 1: x_proj GEMM, double-buffered ----------------
// A=[T*B][512], W_x=[512][2048]; C written transposed [t][n][b]. Also resets g_m/g_bar.
__global__ __launch_bounds__(256) void xproj_gemm(
    const float* __restrict__ A, const float* __restrict__ Bm,
    const float* __restrict__ bias)
{
    __shared__ float As[2][16][132];
    __shared__ float Bs[2][16][128];

    const int tid = threadIdx.x;

    // fold in reset (lstm kernel runs after this one in-stream)
    if (blockIdx.x == 0 && blockIdx.y == 0) {
        if (tid == 0) g_bar = 0;
        for (int i = tid; i < H_SZ * B_SZ; i += 256) g_m[0][i] = 0.0f;
    }

    const int n0 = blockIdx.x * 128;
    const int m0 = blockIdx.y * 128;
    const int tx = tid & 15, ty = tid >> 4;

    const int a_row = tid >> 2;            // 0..63 (second load +64)
    const int a_kq  = (tid & 3) << 2;
    const int b_kr  = tid >> 5;            // 0..7 (second load +8)
    const int b_nq  = (tid & 31) << 2;

    float4 a0, a1, bv0, bv1;
    const float* Aptr0 = A + (size_t)(m0 + a_row) * D_SZ + a_kq;
    const float* Aptr1 = A + (size_t)(m0 + a_row + 64) * D_SZ + a_kq;
    const float* Bptr0 = Bm + (size_t)b_kr * G_SZ + n0 + b_nq;
    const float* Bptr1 = Bm + (size_t)(b_kr + 8) * G_SZ + n0 + b_nq;

    // prologue: k0 = 0
    a0  = *(const float4*)Aptr0;
    a1  = *(const float4*)Aptr1;
    bv0 = *(const float4*)Bptr0;
    bv1 = *(const float4*)Bptr1;
    {
        As[0][a_kq + 0][a_row] = a0.x; As[0][a_kq + 1][a_row] = a0.y;
        As[0][a_kq + 2][a_row] = a0.z; As[0][a_kq + 3][a_row] = a0.w;
        As[0][a_kq + 0][a_row + 64] = a1.x; As[0][a_kq + 1][a_row + 64] = a1.y;
        As[0][a_kq + 2][a_row + 64] = a1.z; As[0][a_kq + 3][a_row + 64] = a1.w;
        *(float4*)&Bs[0][b_kr][b_nq]     = bv0;
        *(float4*)&Bs[0][b_kr + 8][b_nq] = bv1;
    }
    __syncthreads();

    float acc[8][8];
#pragma unroll
    for (int i = 0; i < 8; i++)
#pragma unroll
        for (int j = 0; j < 8; j++) acc[i][j] = 0.0f;

#pragma unroll 2
    for (int it = 0; it < 32; it++) {
        const int st = it & 1;
        if (it < 31) {
            const int k0 = (it + 1) * 16;
            a0  = *(const float4*)(Aptr0 + k0);
            a1  = *(const float4*)(Aptr1 + k0);
            bv0 = *(const float4*)(Bptr0 + (size_t)k0 * G_SZ);
            bv1 = *(const float4*)(Bptr1 + (size_t)k0 * G_SZ);
        }
#pragma unroll
        for (int k = 0; k < 16; k++) {
            float av[8], bv[8];
            *(float4*)&av[0] = *(float4*)&As[st][k][ty * 8];
            *(float4*)&av[4] = *(float4*)&As[st][k][ty * 8 + 4];
            *(float4*)&bv[0] = *(float4*)&Bs[st][k][tx * 8];
            *(float4*)&bv[4] = *(float4*)&Bs[st][k][tx * 8 + 4];
#pragma unroll
            for (int i = 0; i < 8; i++)
#pragma unroll
                for (int j = 0; j < 8; j++) acc[i][j] += av[i] * bv[j];
        }
        if (it < 31) {
            const int sn = st ^ 1;
            As[sn][a_kq + 0][a_row] = a0.x; As[sn][a_kq + 1][a_row] = a0.y;
            As[sn][a_kq + 2][a_row] = a0.z; As[sn][a_kq + 3][a_row] = a0.w;
            As[sn][a_kq + 0][a_row + 64] = a1.x; As[sn][a_kq + 1][a_row + 64] = a1.y;
            As[sn][a_kq + 2][a_row + 64] = a1.z; As[sn][a_kq + 3][a_row + 64] = a1.w;
            *(float4*)&Bs[sn][b_kr][b_nq]     = bv0;
            *(float4*)&Bs[sn][b_kr + 8][b_nq] = bv1;
        }
        __syncthreads();
    }

    // epilogue: [t][n][b]
    const int mrow = m0 + ty * 8;
    const int t  = mrow >> 5;
    const int b0 = mrow & 31;
#pragma unroll
    for (int j = 0; j < 8; j++) {
        int n = n0 + tx * 8 + j;
        float bb = bias[n];
        float4 v0 = make_float4(acc[0][j] + bb, acc[1][j] + bb, acc[2][j] + bb, acc[3][j] + bb);
        float4 v1 = make_float4(acc[4][j] + bb, acc[5][j] + bb, acc[6][j] + bb, acc[7][j] + bb);
        float* dst = g_xproj + ((size_t)t * G_SZ + n) * B_SZ + b0;
        *(float4*)dst       = v0;
        *(float4*)(dst + 4) = v1;
    }
}

// ---------------- phase 2: persistent recurrence ----------------
#define MS_STRIDE 36
#define WS_STRIDE 20
#define SMEM_FLOATS (H_SZ * MS_STRIDE + H_SZ * WS_STRIDE + 16 * B_SZ + 32)

__device__ __forceinline__ float fsig(float x)  { return 1.0f / (1.0f + __expf(-x)); }
__device__ __forceinline__ float ftanh(float x) { return 1.0f - 2.0f / (__expf(2.0f * x) + 1.0f); }

// halving-tree warp reduction round
#define RED_ROUND(OFF, HALF)                                             \
    {                                                                    \
        const bool hi = (l & OFF) != 0;                                  \
        _Pragma("unroll")                                                \
        for (int i = 0; i < HALF; i++) {                                 \
            float send = hi ? v[i] : v[i + HALF];                        \
            float keep = hi ? v[i + HALF] : v[i];                        \
            v[i] = keep + __shfl_xor_sync(0xffffffffu, send, OFF);       \
        }                                                                \
    }

__global__ __launch_bounds__(256, 1) void lstm_kernel(
    const float* __restrict__ paddings,
    const float* __restrict__ W_h,
    float* __restrict__ out,
    int write_final)
{
    extern __shared__ float smem[];
    float* m_s   = smem;                       // [512][36]
    float* w_s   = m_s + H_SZ * MS_STRIDE;     // [512][20]
    float* xp_s  = w_s + H_SZ * WS_STRIDE;     // [16][32]
    float* pad_s = xp_s + 16 * B_SZ;           // [32]

    const unsigned ms_u32 = (unsigned)__cvta_generic_to_shared(m_s);

    const int tid = threadIdx.x;
    const int bid = blockIdx.x;
    const int h_base = bid * 4;

    // W_h slice: cc = j*4+g -> global col g*512 + h_base + j
    for (int idx = tid; idx < H_SZ * 16; idx += 256) {
        int k  = idx >> 4;
        int cc = idx & 15;
        int g  = cc & 3;
        int j  = cc >> 2;
        w_s[k * WS_STRIDE + cc] = W_h[(size_t)k * G_SZ + g * H_SZ + h_base + j];
    }

    const int l  = tid & 31;
    const int w  = tid >> 5;
    const int bt = w & 3;
    const int ct = w >> 2;
    const int b0  = bt * 8;
    const int cc0 = ct * 8;

    // post-reduction ownership: lane l holds outputs (b, cc_a) and (b, cc_a+1)
    const int b_o   = b0 + (l >> 2);
    const int cc_a  = cc0 + ((l & 3) << 1);
    // cell owner = even lanes: (b_o, j_o)
    const int j_o   = ct * 2 + ((l >> 1) & 1);
    const int h_o   = h_base + j_o;

    // xp loader coords
    const int xp_cc = tid >> 3;
    const int xp_q  = (tid & 7) << 2;
    const float* xp_src_base = g_xproj +
        ((size_t)((xp_cc & 3) * H_SZ + h_base + (xp_cc >> 2))) * B_SZ + xp_q;

    float c_reg = 0.0f;

#pragma unroll 1
    for (int s = 0; s < T_STEPS; s++) {
        const float* msrc = g_m[s & 1];

        // m: cp.async in two K-halves
#pragma unroll
        for (int li = 0; li < 8; li++) {
            int idx = tid + li * 256;
            int k = idx >> 3, q = (idx & 7) << 2;
            CP_ASYNC16(ms_u32 + (unsigned)((k * MS_STRIDE + q) * 4), msrc + k * B_SZ + q);
        }
        CP_COMMIT();
#pragma unroll
        for (int li = 8; li < 16; li++) {
            int idx = tid + li * 256;
            int k = idx >> 3, q = (idx & 7) << 2;
            CP_ASYNC16(ms_u32 + (unsigned)((k * MS_STRIDE + q) * 4), msrc + k * B_SZ + q);
        }
        CP_COMMIT();

        // xp slice + paddings (regular loads, latency hidden by cp.async wait)
        float4 xpv;
        if (tid < 128) xpv = *(const float4*)(xp_src_base + (size_t)s * G_SZ * B_SZ);
        float padv = 0.0f;
        if (tid >= 224) padv = paddings[s * B_SZ + (tid - 224)];
        if (tid < 128) *(float4*)&xp_s[xp_cc * B_SZ + xp_q] = xpv;
        if (tid >= 224) pad_s[tid - 224] = padv;

        float v[64];
#pragma unroll
        for (int i = 0; i < 64; i++) v[i] = 0.0f;

        CP_WAIT(1);
        __syncthreads();

        // K 0..255
#pragma unroll
        for (int i = 0; i < 8; i++) {
            int k = (i << 5) + l;
            float mv[8], wv[8];
            *(float4*)&mv[0] = *(float4*)&m_s[k * MS_STRIDE + b0];
            *(float4*)&mv[4] = *(float4*)&m_s[k * MS_STRIDE + b0 + 4];
            *(float4*)&wv[0] = *(float4*)&w_s[k * WS_STRIDE + cc0];
            *(float4*)&wv[4] = *(float4*)&w_s[k * WS_STRIDE + cc0 + 4];
#pragma unroll
            for (int x = 0; x < 8; x++)
#pragma unroll
                for (int y = 0; y < 8; y++) v[x * 8 + y] += mv[x] * wv[y];
        }

        CP_WAIT(0);
        __syncthreads();

        // K 256..511
#pragma unroll
        for (int i = 8; i < 16; i++) {
            int k = (i << 5) + l;
            float mv[8], wv[8];
            *(float4*)&mv[0] = *(float4*)&m_s[k * MS_STRIDE + b0];
            *(float4*)&mv[4] = *(float4*)&m_s[k * MS_STRIDE + b0 + 4];
            *(float4*)&wv[0] = *(float4*)&w_s[k * WS_STRIDE + cc0];
            *(float4*)&wv[4] = *(float4*)&w_s[k * WS_STRIDE + cc0 + 4];
#pragma unroll
            for (int x = 0; x < 8; x++)
#pragma unroll
                for (int y = 0; y < 8; y++) v[x * 8 + y] += mv[x] * wv[y];
        }

        // halving-tree reduction: 62 shfl instead of 320
        RED_ROUND(16, 32)
        RED_ROUND(8, 16)
        RED_ROUND(4, 8)
        RED_ROUND(2, 4)
        RED_ROUND(1, 2)
        // lane l now holds fully-reduced outputs (b_o, cc_a) in v[0], (b_o, cc_a+1) in v[1]

        v[0] += xp_s[cc_a * B_SZ + b_o];
        v[1] += xp_s[(cc_a + 1) * B_SZ + b_o];

        // pair lanes (xor 1): even lane has (i,f), odd has (g,o) for same (b_o, j_o)
        float xg = __shfl_xor_sync(0xffffffffu, v[0], 1);
        float xo = __shfl_xor_sync(0xffffffffu, v[1], 1);

        if ((l & 1) == 0) {
            float p     = pad_s[b_o];
            float mprev = m_s[h_o * MS_STRIDE + b_o];

            float ii = fsig(v[0]), ff = fsig(v[1]);
            float gg = ftanh(xg), oo = fsig(xo);
            float cn = ff * c_reg + ii * gg;
            float mn = oo * ftanh(cn);
            float m2 = mn + (mprev - mn) * p;
            float c2 = cn + (c_reg - cn) * p;
            c_reg = c2;

            g_m[(s + 1) & 1][h_o * B_SZ + b_o] = m2;
            out[((size_t)s * B_SZ + b_o) * H_SZ + h_o] = m2;
            if (write_final && s == T_STEPS - 1) {
                size_t base = (size_t)T_STEPS * B_SZ * H_SZ;
                out[base + (size_t)b_o * H_SZ + h_o] = m2;
                out[base + (size_t)B_SZ * H_SZ + (size_t)b_o * H_SZ + h_o] = c2;
            }
        }

        // ---- grid barrier ----
        __syncthreads();
        if (tid == 0) {
            __threadfence();
            atomicAdd(&g_bar, 1);
            int target = NBLK * (s + 1);
            while (*(volatile int*)&g_bar < target) { }
            __threadfence();
        }
        __syncthreads();
    }
}

// ---------------- launch ----------------
extern "C" void kernel_launch(void* const* d_in, const int* in_sizes, int n_in,
                              void* d_out, int out_size)
{
    const float* input = (const float*)d_in[0];
    const float* padd  = (const float*)d_in[1];
    const float* W_x   = (const float*)d_in[2];
    const float* W_h   = (const float*)d_in[3];
    const float* bias  = (const float*)d_in[4];
    float* out = (float*)d_out;

    const size_t smem_bytes = (size_t)SMEM_FLOATS * sizeof(float);
    cudaFuncSetAttribute(lstm_kernel, cudaFuncAttributeMaxDynamicSharedMemorySize,
                         (int)smem_bytes);

    int write_final =
        ((size_t)out_size >= (size_t)T_STEPS * B_SZ * H_SZ + 2u * B_SZ * H_SZ) ? 1 : 0;

    xproj_gemm<<<dim3(G_SZ / 128, (T_STEPS * B_SZ) / 128), 256>>>(input, W_x, bias);
    lstm_kernel<<<NBLK, 256, smem_bytes>>>(padd, W_h, out, write_final);
}

// round 3
// speedup vs baseline: 1.1123x; 1.0748x over previous
#include <cuda_runtime.h>
#include <cuda_bf16.h>
#include <cstdint>

#define T_STEPS 2048
#define B_SZ    32
#define D_SZ    512
#define H_SZ    512
#define G_SZ    2048
#define NBLK    128

// ---------------- device scratch ----------------
__device__ float g_xproj[(size_t)T_STEPS * G_SZ * B_SZ];   // [T][4H][B]
__device__ float g_m[2][H_SZ * B_SZ];                      // [h][b]
__device__ int   g_bar;

// ---------------- cp.async helpers ----------------
#define CP_ASYNC16(dst_u32, src_ptr) \
    asm volatile("cp.async.cg.shared.global [%0], [%1], 16;\n" :: "r"(dst_u32), "l"(src_ptr))
#define CP_COMMIT() asm volatile("cp.async.commit_group;\n")
#define CP_WAIT(N)  asm volatile("cp.async.wait_group %0;\n" :: "n"(N))

// ---------------- tf32 helpers ----------------
__device__ __forceinline__ uint32_t f2tf(float x) {
    uint32_t r;
    asm("cvt.rna.tf32.f32 %0, %1;" : "=r"(r) : "f"(x));
    return r;
}
__device__ __forceinline__ void mma_tf32(float& d0, float& d1, float& d2, float& d3,
                                         uint32_t a0, uint32_t a1, uint32_t a2, uint32_t a3,
                                         uint32_t b0, uint32_t b1) {
    asm volatile(
        "mma.sync.aligned.m16n8k8.row.col.f32.tf32.tf32.f32 "
        "{%0,%1,%2,%3},{%4,%5,%6,%7},{%8,%9},{%0,%1,%2,%3};"
        : "+f"(d0), "+f"(d1), "+f"(d2), "+f"(d3)
        : "r"(a0), "r"(a1), "r"(a2), "r"(a3), "r"(b0), "r"(b1));
}

// ---------------- phase 1: x_proj GEMM (unchanged, fp32 SIMT) ----------------
__global__ __launch_bounds__(256) void xproj_gemm(
    const float* __restrict__ A, const float* __restrict__ Bm,
    const float* __restrict__ bias)
{
    __shared__ float As[2][16][132];
    __shared__ float Bs[2][16][128];

    const int tid = threadIdx.x;

    if (blockIdx.x == 0 && blockIdx.y == 0) {
        if (tid == 0) g_bar = 0;
        for (int i = tid; i < H_SZ * B_SZ; i += 256) g_m[0][i] = 0.0f;
    }

    const int n0 = blockIdx.x * 128;
    const int m0 = blockIdx.y * 128;
    const int tx = tid & 15, ty = tid >> 4;

    const int a_row = tid >> 2;
    const int a_kq  = (tid & 3) << 2;
    const int b_kr  = tid >> 5;
    const int b_nq  = (tid & 31) << 2;

    float4 a0, a1, bv0, bv1;
    const float* Aptr0 = A + (size_t)(m0 + a_row) * D_SZ + a_kq;
    const float* Aptr1 = A + (size_t)(m0 + a_row + 64) * D_SZ + a_kq;
    const float* Bptr0 = Bm + (size_t)b_kr * G_SZ + n0 + b_nq;
    const float* Bptr1 = Bm + (size_t)(b_kr + 8) * G_SZ + n0 + b_nq;

    a0  = *(const float4*)Aptr0;
    a1  = *(const float4*)Aptr1;
    bv0 = *(const float4*)Bptr0;
    bv1 = *(const float4*)Bptr1;
    {
        As[0][a_kq + 0][a_row] = a0.x; As[0][a_kq + 1][a_row] = a0.y;
        As[0][a_kq + 2][a_row] = a0.z; As[0][a_kq + 3][a_row] = a0.w;
        As[0][a_kq + 0][a_row + 64] = a1.x; As[0][a_kq + 1][a_row + 64] = a1.y;
        As[0][a_kq + 2][a_row + 64] = a1.z; As[0][a_kq + 3][a_row + 64] = a1.w;
        *(float4*)&Bs[0][b_kr][b_nq]     = bv0;
        *(float4*)&Bs[0][b_kr + 8][b_nq] = bv1;
    }
    __syncthreads();

    float acc[8][8];
#pragma unroll
    for (int i = 0; i < 8; i++)
#pragma unroll
        for (int j = 0; j < 8; j++) acc[i][j] = 0.0f;

#pragma unroll 2
    for (int it = 0; it < 32; it++) {
        const int st = it & 1;
        if (it < 31) {
            const int k0 = (it + 1) * 16;
            a0  = *(const float4*)(Aptr0 + k0);
            a1  = *(const float4*)(Aptr1 + k0);
            bv0 = *(const float4*)(Bptr0 + (size_t)k0 * G_SZ);
            bv1 = *(const float4*)(Bptr1 + (size_t)k0 * G_SZ);
        }
#pragma unroll
        for (int k = 0; k < 16; k++) {
            float av[8], bv[8];
            *(float4*)&av[0] = *(float4*)&As[st][k][ty * 8];
            *(float4*)&av[4] = *(float4*)&As[st][k][ty * 8 + 4];
            *(float4*)&bv[0] = *(float4*)&Bs[st][k][tx * 8];
            *(float4*)&bv[4] = *(float4*)&Bs[st][k][tx * 8 + 4];
#pragma unroll
            for (int i = 0; i < 8; i++)
#pragma unroll
                for (int j = 0; j < 8; j++) acc[i][j] += av[i] * bv[j];
        }
        if (it < 31) {
            const int sn = st ^ 1;
            As[sn][a_kq + 0][a_row] = a0.x; As[sn][a_kq + 1][a_row] = a0.y;
            As[sn][a_kq + 2][a_row] = a0.z; As[sn][a_kq + 3][a_row] = a0.w;
            As[sn][a_kq + 0][a_row + 64] = a1.x; As[sn][a_kq + 1][a_row + 64] = a1.y;
            As[sn][a_kq + 2][a_row + 64] = a1.z; As[sn][a_kq + 3][a_row + 64] = a1.w;
            *(float4*)&Bs[sn][b_kr][b_nq]     = bv0;
            *(float4*)&Bs[sn][b_kr + 8][b_nq] = bv1;
        }
        __syncthreads();
    }

    const int mrow = m0 + ty * 8;
    const int t  = mrow >> 5;
    const int b0 = mrow & 31;
#pragma unroll
    for (int j = 0; j < 8; j++) {
        int n = n0 + tx * 8 + j;
        float bb = bias[n];
        float4 v0 = make_float4(acc[0][j] + bb, acc[1][j] + bb, acc[2][j] + bb, acc[3][j] + bb);
        float4 v1 = make_float4(acc[4][j] + bb, acc[5][j] + bb, acc[6][j] + bb, acc[7][j] + bb);
        float* dst = g_xproj + ((size_t)t * G_SZ + n) * B_SZ + b0;
        *(float4*)dst       = v0;
        *(float4*)(dst + 4) = v1;
    }
}

// ---------------- phase 2: persistent recurrence (tensor-core 3xTF32) -------
#define MS 40   // m_s row stride (k*40+b): conflict-free for A-fragment LDS
#define SMEM_FLOATS (H_SZ * MS + 8 * 512 + 512 + 512 + 32)

__device__ __forceinline__ float fsig(float x)  { return 1.0f / (1.0f + __expf(-x)); }
__device__ __forceinline__ float ftanh(float x) { return 1.0f - 2.0f / (__expf(2.0f * x) + 1.0f); }

__global__ __launch_bounds__(256, 1) void lstm_kernel(
    const float* __restrict__ paddings,
    const float* __restrict__ W_h,
    float* __restrict__ out,
    int write_final)
{
    extern __shared__ float smem[];
    float* m_s   = smem;                     // [512][40]
    float* red   = m_s + H_SZ * MS;          // [8][512]
    float* gsum  = red + 8 * 512;            // [512]
    float* xp_s  = gsum + 512;               // [16cc][32b]
    float* pad_s = xp_s + 512;               // [32]

    const unsigned ms_u32 = (unsigned)__cvta_generic_to_shared(m_s);

    const int tid = threadIdx.x;
    const int bid = blockIdx.x;
    const int h_base = bid * 4;

    const int l   = tid & 31;
    const int w   = tid >> 5;
    const int gid = l >> 2;      // 0..7
    const int tig = l & 3;       // 0..3

    // ---- W fragments, hi/lo tf32 split, resident in registers ----
    // warp w owns k-tiles kt = j*8 + w (j=0..7); cc = j4+g maps to global col g*512+h_base+j4
    uint32_t Whi[8][2][2], Wlo[8][2][2];
#pragma unroll
    for (int j = 0; j < 8; j++)
#pragma unroll
        for (int nt = 0; nt < 2; nt++)
#pragma unroll
            for (int r = 0; r < 2; r++) {
                int k  = j * 64 + w * 8 + tig + r * 4;
                int cc = nt * 8 + gid;
                int g  = cc & 3;
                int j4 = cc >> 2;
                float wv = W_h[(size_t)k * G_SZ + g * H_SZ + h_base + j4];
                uint32_t hi = f2tf(wv);
                Whi[j][nt][r] = hi;
                Wlo[j][nt][r] = f2tf(wv - __uint_as_float(hi));
            }

    // cell ownership: tid<128 -> (b=tid&31, j=tid>>5)
    const int cb  = tid & 31;
    const int cj  = tid >> 5;
    const int h_o = h_base + cj;

    // xp loader coords (tid<128)
    const int xp_cc = tid >> 3;
    const int xp_q  = (tid & 7) << 2;
    const float* xp_src_base = g_xproj +
        ((size_t)((xp_cc & 3) * H_SZ + h_base + (xp_cc >> 2))) * B_SZ + xp_q;

    float c_reg = 0.0f;

#pragma unroll 1
    for (int s = 0; s < T_STEPS; s++) {
        const float* msrc = g_m[s & 1];

        // m -> smem via cp.async, two K-halves
#pragma unroll
        for (int li = 0; li < 8; li++) {
            int idx = tid + li * 256;
            int k = idx >> 3, q = (idx & 7) << 2;
            CP_ASYNC16(ms_u32 + (unsigned)((k * MS + q) * 4), msrc + k * B_SZ + q);
        }
        CP_COMMIT();
#pragma unroll
        for (int li = 8; li < 16; li++) {
            int idx = tid + li * 256;
            int k = idx >> 3, q = (idx & 7) << 2;
            CP_ASYNC16(ms_u32 + (unsigned)((k * MS + q) * 4), msrc + k * B_SZ + q);
        }
        CP_COMMIT();

        // xp slice + paddings
        float4 xpv;
        if (tid < 128) xpv = *(const float4*)(xp_src_base + (size_t)s * G_SZ * B_SZ);
        float padv = 0.0f;
        if (tid >= 224) padv = paddings[s * B_SZ + (tid - 224)];
        if (tid < 128) *(float4*)&xp_s[xp_cc * B_SZ + xp_q] = xpv;
        if (tid >= 224) pad_s[tid - 224] = padv;

        float acc1[2][2][4];   // hi*hi
        float acc2[2][2][4];   // hi*lo + lo*hi
#pragma unroll
        for (int mt = 0; mt < 2; mt++)
#pragma unroll
            for (int nt = 0; nt < 2; nt++)
#pragma unroll
                for (int r = 0; r < 4; r++) { acc1[mt][nt][r] = 0.0f; acc2[mt][nt][r] = 0.0f; }

        CP_WAIT(1);
        __syncthreads();

#pragma unroll
        for (int j = 0; j < 8; j++) {
            if (j == 4) { CP_WAIT(0); __syncthreads(); }
            const int kb = j * 64 + w * 8 + tig;
            const float* mp0 = &m_s[kb * MS];
            const float* mp4 = &m_s[(kb + 4) * MS];
#pragma unroll
            for (int mt = 0; mt < 2; mt++) {
                const int b = mt * 16 + gid;
                float x0 = mp0[b], x1 = mp0[b + 8];
                float x2 = mp4[b], x3 = mp4[b + 8];
                uint32_t a0h = f2tf(x0), a1h = f2tf(x1), a2h = f2tf(x2), a3h = f2tf(x3);
                uint32_t a0l = f2tf(x0 - __uint_as_float(a0h));
                uint32_t a1l = f2tf(x1 - __uint_as_float(a1h));
                uint32_t a2l = f2tf(x2 - __uint_as_float(a2h));
                uint32_t a3l = f2tf(x3 - __uint_as_float(a3h));
#pragma unroll
                for (int nt = 0; nt < 2; nt++) {
                    mma_tf32(acc1[mt][nt][0], acc1[mt][nt][1], acc1[mt][nt][2], acc1[mt][nt][3],
                             a0h, a1h, a2h, a3h, Whi[j][nt][0], Whi[j][nt][1]);
                    mma_tf32(acc2[mt][nt][0], acc2[mt][nt][1], acc2[mt][nt][2], acc2[mt][nt][3],
                             a0h, a1h, a2h, a3h, Wlo[j][nt][0], Wlo[j][nt][1]);
                    mma_tf32(acc2[mt][nt][0], acc2[mt][nt][1], acc2[mt][nt][2], acc2[mt][nt][3],
                             a0l, a1l, a2l, a3l, Whi[j][nt][0], Whi[j][nt][1]);
                }
            }
        }

        // partials -> red[w][cc][b]
#pragma unroll
        for (int mt = 0; mt < 2; mt++)
#pragma unroll
            for (int nt = 0; nt < 2; nt++) {
                const int b  = mt * 16 + gid;
                const int cc = nt * 8 + tig * 2;
                float* rp = red + w * 512;
                rp[cc * 32 + b]           = acc1[mt][nt][0] + acc2[mt][nt][0];
                rp[(cc + 1) * 32 + b]     = acc1[mt][nt][1] + acc2[mt][nt][1];
                rp[cc * 32 + b + 8]       = acc1[mt][nt][2] + acc2[mt][nt][2];
                rp[(cc + 1) * 32 + b + 8] = acc1[mt][nt][3] + acc2[mt][nt][3];
            }
        __syncthreads();

        // 8-way K reduction + xp
#pragma unroll
        for (int rep = 0; rep < 2; rep++) {
            int o = tid + rep * 256;
            float ssum = xp_s[o];
#pragma unroll
            for (int ww = 0; ww < 8; ww++) ssum += red[ww * 512 + o];
            gsum[o] = ssum;
        }
        __syncthreads();

        // cell update (tid < 128)
        if (tid < 128) {
            float xi = gsum[(cj * 4 + 0) * 32 + cb];
            float xf = gsum[(cj * 4 + 1) * 32 + cb];
            float xg = gsum[(cj * 4 + 2) * 32 + cb];
            float xo = gsum[(cj * 4 + 3) * 32 + cb];
            float p     = pad_s[cb];
            float mprev = m_s[h_o * MS + cb];

            float ii = fsig(xi), ff = fsig(xf), gg = ftanh(xg), oo = fsig(xo);
            float cn = ff * c_reg + ii * gg;
            float mn = oo * ftanh(cn);
            float m2 = mn + (mprev - mn) * p;
            float c2 = cn + (c_reg - cn) * p;
            c_reg = c2;

            g_m[(s + 1) & 1][h_o * B_SZ + cb] = m2;
            out[((size_t)s * B_SZ + cb) * H_SZ + h_o] = m2;
            if (write_final && s == T_STEPS - 1) {
                size_t base = (size_t)T_STEPS * B_SZ * H_SZ;
                out[base + (size_t)cb * H_SZ + h_o] = m2;
                out[base + (size_t)B_SZ * H_SZ + (size_t)cb * H_SZ + h_o] = c2;
            }
        }

        // ---- grid barrier ----
        __syncthreads();
        if (tid == 0) {
            __threadfence();
            atomicAdd(&g_bar, 1);
            int target = NBLK * (s + 1);
            while (*(volatile int*)&g_bar < target) { }
            __threadfence();
        }
        __syncthreads();
    }
}

// ---------------- launch ----------------
extern "C" void kernel_launch(void* const* d_in, const int* in_sizes, int n_in,
                              void* d_out, int out_size)
{
    const float* input = (const float*)d_in[0];
    const float* padd  = (const float*)d_in[1];
    const float* W_x   = (const float*)d_in[2];
    const float* W_h   = (const float*)d_in[3];
    const float* bias  = (const float*)d_in[4];
    float* out = (float*)d_out;

    const size_t smem_bytes = (size_t)SMEM_FLOATS * sizeof(float);
    cudaFuncSetAttribute(lstm_kernel, cudaFuncAttributeMaxDynamicSharedMemorySize,
                         (int)smem_bytes);

    int write_final =
        ((size_t)out_size >= (size_t)T_STEPS * B_SZ * H_SZ + 2u * B_SZ * H_SZ) ? 1 : 0;

    xproj_gemm<<<dim3(G_SZ / 128, (T_STEPS * B_SZ) / 128), 256>>>(input, W_x, bias);
    lstm_kernel<<<NBLK, 256, smem_bytes>>>(padd, W_h, out, write_final);
}

// round 4
// speedup vs baseline: 1.3323x; 1.1978x over previous
#include <cuda_runtime.h>
#include <cuda_bf16.h>
#include <cstdint>

#define T_STEPS 2048
#define B_SZ    32
#define D_SZ    512
#define H_SZ    512
#define G_SZ    2048
#define NBLK    128

// ---------------- device scratch ----------------
__device__ float g_xproj[(size_t)T_STEPS * G_SZ * B_SZ];   // [T][4H][B]
__device__ float g_m[2][H_SZ * B_SZ];                      // [h][b]
__device__ int   g_bar;

// ---------------- helpers ----------------
#define CP_ASYNC16(dst_u32, src_ptr) \
    asm volatile("cp.async.cg.shared.global [%0], [%1], 16;\n" :: "r"(dst_u32), "l"(src_ptr))
#define CP_COMMIT() asm volatile("cp.async.commit_group;\n")
#define CP_WAIT(N)  asm volatile("cp.async.wait_group %0;\n" :: "n"(N))

__device__ __forceinline__ void split_tf(float x, uint32_t& hi, uint32_t& lo) {
    uint32_t h = __float_as_uint(x) & 0xffffe000u;   // exact truncation to tf32 bits
    hi = h;
    lo = __float_as_uint(x - __uint_as_float(h));    // exact residual (HW truncates low bits)
}
__device__ __forceinline__ void mma_tf32(float& d0, float& d1, float& d2, float& d3,
                                         uint32_t a0, uint32_t a1, uint32_t a2, uint32_t a3,
                                         uint32_t b0, uint32_t b1) {
    asm volatile(
        "mma.sync.aligned.m16n8k8.row.col.f32.tf32.tf32.f32 "
        "{%0,%1,%2,%3},{%4,%5,%6,%7},{%8,%9},{%0,%1,%2,%3};"
        : "+f"(d0), "+f"(d1), "+f"(d2), "+f"(d3)
        : "r"(a0), "r"(a1), "r"(a2), "r"(a3), "r"(b0), "r"(b1));
}

// ============ phase 1: x_proj GEMM on tensor cores (3xTF32) ============
// Block tile: M=64 (rows of A = t*32+b), N=128, K=512 in 16 chunks of 32.
// C written transposed to g_xproj[t][n][b].
#define XP_AS_FL (2 * 64 * 36)     // [buf][m][36]
#define XP_BS_FL (2 * 32 * 136)    // [buf][k][136]
#define XP_SMEM_FL (XP_AS_FL + XP_BS_FL)

__global__ __launch_bounds__(256) void xproj_gemm(
    const float* __restrict__ A, const float* __restrict__ Bm,
    const float* __restrict__ bias)
{
    extern __shared__ float sm[];
    float* As = sm;                 // 4608 floats
    float* Bs = sm + XP_AS_FL;      // 8704 floats
    float* stage = Bs;              // overlay for epilogue (8704 >= 128*68)

    const unsigned as_u32 = (unsigned)__cvta_generic_to_shared(As);
    const unsigned bs_u32 = (unsigned)__cvta_generic_to_shared(Bs);

    const int tid = threadIdx.x;

    if (blockIdx.x == 0 && blockIdx.y == 0) {   // fold reset
        if (tid == 0) g_bar = 0;
        for (int i = tid; i < H_SZ * B_SZ; i += 256) g_m[0][i] = 0.0f;
    }

    const int n0 = blockIdx.x * 128;
    const int m0 = blockIdx.y * 64;
    const int w   = tid >> 5;
    const int l   = tid & 31;
    const int gid = l >> 2;
    const int tig = l & 3;
    const int nw  = w * 16;

    // load coords
    const int am = tid >> 3, akq = (tid & 7) << 2;            // +32 rows on second
    const int bk = tid >> 6, bnq = (tid & 63) << 1;           // unused; use below scheme

    // issue one K-chunk (32) into buffer `buf`
    auto issue = [&](int it, int buf) {
        const int kc = it * 32;
#pragma unroll
        for (int i = 0; i < 2; i++) {
            int idx = tid + i * 256;
            int m = idx >> 3, kq = (idx & 7) << 2;
            CP_ASYNC16(as_u32 + (unsigned)(((buf * 64 + m) * 36 + kq) * 4),
                       A + (size_t)(m0 + m) * D_SZ + kc + kq);
        }
#pragma unroll
        for (int i = 0; i < 4; i++) {
            int idx = tid + i * 256;
            int k = idx >> 5, nq = (idx & 31) << 2;
            CP_ASYNC16(bs_u32 + (unsigned)(((buf * 32 + k) * 136 + nq) * 4),
                       Bm + (size_t)(kc + k) * G_SZ + n0 + nq);
        }
        CP_COMMIT();
    };

    float acc1[4][2][4], acc2[4][2][4];
#pragma unroll
    for (int mt = 0; mt < 4; mt++)
#pragma unroll
        for (int nt = 0; nt < 2; nt++)
#pragma unroll
            for (int r = 0; r < 4; r++) { acc1[mt][nt][r] = 0.0f; acc2[mt][nt][r] = 0.0f; }

    issue(0, 0);

#pragma unroll 1
    for (int it = 0; it < 16; it++) {
        if (it < 15) issue(it + 1, (it + 1) & 1);
        if (it < 15) { CP_WAIT(1); } else { CP_WAIT(0); }
        __syncthreads();

        const float* Ab = As + (it & 1) * (64 * 36);
        const float* Bb = Bs + (it & 1) * (32 * 136);

#pragma unroll
        for (int kt = 0; kt < 4; kt++) {
            uint32_t bh[2][2], bl[2][2];
#pragma unroll
            for (int nt = 0; nt < 2; nt++) {
                float w0 = Bb[(kt * 8 + tig) * 136 + nw + nt * 8 + gid];
                float w1 = Bb[(kt * 8 + tig + 4) * 136 + nw + nt * 8 + gid];
                split_tf(w0, bh[nt][0], bl[nt][0]);
                split_tf(w1, bh[nt][1], bl[nt][1]);
            }
#pragma unroll
            for (int mt = 0; mt < 4; mt++) {
                float x0 = Ab[(mt * 16 + gid) * 36 + kt * 8 + tig];
                float x1 = Ab[(mt * 16 + gid + 8) * 36 + kt * 8 + tig];
                float x2 = Ab[(mt * 16 + gid) * 36 + kt * 8 + tig + 4];
                float x3 = Ab[(mt * 16 + gid + 8) * 36 + kt * 8 + tig + 4];
                uint32_t ah0, al0, ah1, al1, ah2, al2, ah3, al3;
                split_tf(x0, ah0, al0); split_tf(x1, ah1, al1);
                split_tf(x2, ah2, al2); split_tf(x3, ah3, al3);
#pragma unroll
                for (int nt = 0; nt < 2; nt++) {
                    mma_tf32(acc1[mt][nt][0], acc1[mt][nt][1], acc1[mt][nt][2], acc1[mt][nt][3],
                             ah0, ah1, ah2, ah3, bh[nt][0], bh[nt][1]);
                    mma_tf32(acc2[mt][nt][0], acc2[mt][nt][1], acc2[mt][nt][2], acc2[mt][nt][3],
                             ah0, ah1, ah2, ah3, bl[nt][0], bl[nt][1]);
                    mma_tf32(acc2[mt][nt][0], acc2[mt][nt][1], acc2[mt][nt][2], acc2[mt][nt][3],
                             al0, al1, al2, al3, bh[nt][0], bh[nt][1]);
                }
            }
        }
        __syncthreads();
    }

    // epilogue: fragments -> stage[n][68] -> transposed global [t][n][b]
#pragma unroll
    for (int mt = 0; mt < 4; mt++)
#pragma unroll
        for (int nt = 0; nt < 2; nt++) {
            int m = mt * 16 + gid;
            int n = nw + nt * 8 + tig * 2;
            stage[n * 68 + m]           = acc1[mt][nt][0] + acc2[mt][nt][0];
            stage[(n + 1) * 68 + m]     = acc1[mt][nt][1] + acc2[mt][nt][1];
            stage[n * 68 + m + 8]       = acc1[mt][nt][2] + acc2[mt][nt][2];
            stage[(n + 1) * 68 + m + 8] = acc1[mt][nt][3] + acc2[mt][nt][3];
        }
    __syncthreads();

#pragma unroll
    for (int i = 0; i < 8; i++) {
        int idx = tid + i * 256;
        int n = idx >> 4, mq = (idx & 15) << 2;
        float4 v = *(float4*)&stage[n * 68 + mq];
        float bb = bias[n0 + n];
        v.x += bb; v.y += bb; v.z += bb; v.w += bb;
        int mg = m0 + mq;
        int t = mg >> 5, b = mg & 31;
        *(float4*)&g_xproj[((size_t)t * G_SZ + n0 + n) * B_SZ + b] = v;
    }
}

// ============ phase 2: persistent recurrence (512 thr, 16-way K-split) ======
#define MS 40
#define RED_OFF   (H_SZ * MS)                  // 20480
#define GSUM_OFF  (RED_OFF + 16 * 16 * 36)     // +9216
#define XP_OFF    (GSUM_OFF + 512)
#define PAD_OFF   (XP_OFF + 2 * 512)
#define SMEM_FLOATS_L (PAD_OFF + 2 * 32)

__device__ __forceinline__ float fsig(float x)  { return 1.0f / (1.0f + __expf(-x)); }
__device__ __forceinline__ float ftanh(float x) { return 1.0f - 2.0f / (__expf(2.0f * x) + 1.0f); }

__global__ __launch_bounds__(512, 1) void lstm_kernel(
    const float* __restrict__ paddings,
    const float* __restrict__ W_h,
    float* __restrict__ out,
    int write_final)
{
    extern __shared__ float smem[];
    float* m_s   = smem;
    float* red   = smem + RED_OFF;    // [16 w][16 cc][36]
    float* gsum  = smem + GSUM_OFF;   // [512]
    float* xp_s  = smem + XP_OFF;     // [2][16cc][32b]
    float* pad_s = smem + PAD_OFF;    // [2][32]

    const unsigned ms_u32  = (unsigned)__cvta_generic_to_shared(m_s);
    const unsigned xp_u32  = (unsigned)__cvta_generic_to_shared(xp_s);
    const unsigned pad_u32 = (unsigned)__cvta_generic_to_shared(pad_s);

    const int tid = threadIdx.x;
    const int bid = blockIdx.x;
    const int h_base = bid * 4;

    const int l   = tid & 31;
    const int w   = tid >> 5;      // 0..15
    const int gid = l >> 2;
    const int tig = l & 3;

    // W fragments: warp w owns ktiles kb = j*128 + w*8 (j=0..3)
    uint32_t Whi[4][2][2], Wlo[4][2][2];
#pragma unroll
    for (int j = 0; j < 4; j++)
#pragma unroll
        for (int nt = 0; nt < 2; nt++)
#pragma unroll
            for (int r = 0; r < 2; r++) {
                int k  = j * 128 + w * 8 + tig + r * 4;
                int cc = nt * 8 + gid;
                int g  = cc & 3;
                int j4 = cc >> 2;
                float wv = W_h[(size_t)k * G_SZ + g * H_SZ + h_base + j4];
                split_tf(wv, Whi[j][nt][r], Wlo[j][nt][r]);
            }

    // cell ownership (tid<128): b=tid&31, j=tid>>5
    const int cb  = tid & 31;
    const int cj  = tid >> 5;
    const int h_o = h_base + cj;

    // xp loader coords (tid<128)
    const int xp_cc = tid >> 3;
    const int xp_q  = (tid & 7) << 2;
    const float* xp_src_base = g_xproj +
        ((size_t)((xp_cc & 3) * H_SZ + h_base + (xp_cc >> 2))) * B_SZ + xp_q;

    // prologue: prefetch xp(0) + pad(0)  (group A)
    if (tid < 128)
        CP_ASYNC16(xp_u32 + (unsigned)((xp_cc * B_SZ + xp_q) * 4), xp_src_base);
    if (tid >= 128 && tid < 136)
        CP_ASYNC16(pad_u32 + (unsigned)((tid - 128) * 16), paddings + (tid - 128) * 4);
    CP_COMMIT();

    float c_reg = 0.0f;

#pragma unroll 1
    for (int s = 0; s < T_STEPS; s++) {
        const float* msrc = g_m[s & 1];
        const int pb = s & 1, nb = pb ^ 1;

        // G1: m rows 0..255
#pragma unroll
        for (int li = 0; li < 4; li++) {
            int idx = tid + li * 512;
            int k = idx >> 3, q = (idx & 7) << 2;
            CP_ASYNC16(ms_u32 + (unsigned)((k * MS + q) * 4), msrc + k * B_SZ + q);
        }
        CP_COMMIT();
        // G2: m rows 256..511
#pragma unroll
        for (int li = 4; li < 8; li++) {
            int idx = tid + li * 512;
            int k = idx >> 3, q = (idx & 7) << 2;
            CP_ASYNC16(ms_u32 + (unsigned)((k * MS + q) * 4), msrc + k * B_SZ + q);
        }
        CP_COMMIT();
        // G3: prefetch xp(s+1) + pad(s+1)
        if (s + 1 < T_STEPS) {
            if (tid < 128)
                CP_ASYNC16(xp_u32 + (unsigned)(((nb * 512) + xp_cc * B_SZ + xp_q) * 4),
                           xp_src_base + (size_t)(s + 1) * G_SZ * B_SZ);
            if (tid >= 128 && tid < 136)
                CP_ASYNC16(pad_u32 + (unsigned)((nb * 32 + (tid - 128) * 4) * 4),
                           paddings + (size_t)(s + 1) * B_SZ + (tid - 128) * 4);
        }
        CP_COMMIT();

        float acc1[2][2][4], acc2[2][2][4];
#pragma unroll
        for (int mt = 0; mt < 2; mt++)
#pragma unroll
            for (int nt = 0; nt < 2; nt++)
#pragma unroll
                for (int r = 0; r < 4; r++) { acc1[mt][nt][r] = 0.0f; acc2[mt][nt][r] = 0.0f; }

        CP_WAIT(2);          // G1 ready (and prev G3)
        __syncthreads();

#pragma unroll
        for (int j = 0; j < 4; j++) {
            if (j == 2) { CP_WAIT(1); __syncthreads(); }
            const int kb = j * 128 + w * 8 + tig;
            const float* mp0 = &m_s[kb * MS];
            const float* mp4 = &m_s[(kb + 4) * MS];
#pragma unroll
            for (int mt = 0; mt < 2; mt++) {
                const int b = mt * 16 + gid;
                float x0 = mp0[b], x1 = mp0[b + 8];
                float x2 = mp4[b], x3 = mp4[b + 8];
                uint32_t ah0, al0, ah1, al1, ah2, al2, ah3, al3;
                split_tf(x0, ah0, al0); split_tf(x1, ah1, al1);
                split_tf(x2, ah2, al2); split_tf(x3, ah3, al3);
#pragma unroll
                for (int nt = 0; nt < 2; nt++) {
                    mma_tf32(acc1[mt][nt][0], acc1[mt][nt][1], acc1[mt][nt][2], acc1[mt][nt][3],
                             ah0, ah1, ah2, ah3, Whi[j][nt][0], Whi[j][nt][1]);
                    mma_tf32(acc2[mt][nt][0], acc2[mt][nt][1], acc2[mt][nt][2], acc2[mt][nt][3],
                             ah0, ah1, ah2, ah3, Wlo[j][nt][0], Wlo[j][nt][1]);
                    mma_tf32(acc2[mt][nt][0], acc2[mt][nt][1], acc2[mt][nt][2], acc2[mt][nt][3],
                             al0, al1, al2, al3, Whi[j][nt][0], Whi[j][nt][1]);
                }
            }
        }

        // partials -> red[w][cc][36] (conflict-free: 2*36 % 32 == 8)
        {
            float* rp = red + w * 576;
#pragma unroll
            for (int mt = 0; mt < 2; mt++)
#pragma unroll
                for (int nt = 0; nt < 2; nt++) {
                    const int b  = mt * 16 + gid;
                    const int cc = nt * 8 + tig * 2;
                    rp[cc * 36 + b]           = acc1[mt][nt][0] + acc2[mt][nt][0];
                    rp[(cc + 1) * 36 + b]     = acc1[mt][nt][1] + acc2[mt][nt][1];
                    rp[cc * 36 + b + 8]       = acc1[mt][nt][2] + acc2[mt][nt][2];
                    rp[(cc + 1) * 36 + b + 8] = acc1[mt][nt][3] + acc2[mt][nt][3];
                }
        }
        __syncthreads();

        // 16-way K reduction + xp  (one output per thread)
        {
            const int occ = tid >> 5, ob = tid & 31;
            float ssum = xp_s[pb * 512 + tid];
#pragma unroll
            for (int ww = 0; ww < 16; ww++) ssum += red[ww * 576 + occ * 36 + ob];
            gsum[tid] = ssum;
        }
        __syncthreads();

        // cell update
        float m2 = 0.0f, c2 = 0.0f;
        if (tid < 128) {
            float xi = gsum[(cj * 4 + 0) * 32 + cb];
            float xf = gsum[(cj * 4 + 1) * 32 + cb];
            float xg = gsum[(cj * 4 + 2) * 32 + cb];
            float xo = gsum[(cj * 4 + 3) * 32 + cb];
            float p     = pad_s[pb * 32 + cb];
            float mprev = m_s[h_o * MS + cb];

            float ii = fsig(xi), ff = fsig(xf), gg = ftanh(xg), oo = fsig(xo);
            float cn = ff * c_reg + ii * gg;
            float mn = oo * ftanh(cn);
            m2 = mn + (mprev - mn) * p;
            c2 = cn + (c_reg - cn) * p;
            c_reg = c2;
            g_m[(s + 1) & 1][h_o * B_SZ + cb] = m2;
        }

        // ---- barrier: arrive early, overlap out-store with arrival skew ----
        __syncthreads();
        if (tid == 0) { __threadfence(); atomicAdd(&g_bar, 1); }
        if (tid < 128) {
            out[((size_t)s * B_SZ + cb) * H_SZ + h_o] = m2;
            if (write_final && s == T_STEPS - 1) {
                size_t base = (size_t)T_STEPS * B_SZ * H_SZ;
                out[base + (size_t)cb * H_SZ + h_o] = m2;
                out[base + (size_t)B_SZ * H_SZ + (size_t)cb * H_SZ + h_o] = c2;
            }
        }
        if (tid == 0) {
            int target = NBLK * (s + 1);
            while (*(volatile int*)&g_bar < target) { }
            __threadfence();
        }
        __syncthreads();
    }
}

// ---------------- launch ----------------
extern "C" void kernel_launch(void* const* d_in, const int* in_sizes, int n_in,
                              void* d_out, int out_size)
{
    const float* input = (const float*)d_in[0];
    const float* padd  = (const float*)d_in[1];
    const float* W_x   = (const float*)d_in[2];
    const float* W_h   = (const float*)d_in[3];
    const float* bias  = (const float*)d_in[4];
    float* out = (float*)d_out;

    const size_t xp_smem = (size_t)XP_SMEM_FL * sizeof(float);
    const size_t ls_smem = (size_t)SMEM_FLOATS_L * sizeof(float);
    cudaFuncSetAttribute(xproj_gemm, cudaFuncAttributeMaxDynamicSharedMemorySize, (int)xp_smem);
    cudaFuncSetAttribute(lstm_kernel, cudaFuncAttributeMaxDynamicSharedMemorySize, (int)ls_smem);

    int write_final =
        ((size_t)out_size >= (size_t)T_STEPS * B_SZ * H_SZ + 2u * B_SZ * H_SZ) ? 1 : 0;

    xproj_gemm<<<dim3(G_SZ / 128, (T_STEPS * B_SZ) / 64), 256, xp_smem>>>(input, W_x, bias);
    lstm_kernel<<<NBLK, 512, ls_smem>>>(padd, W_h, out, write_final);
}